// round 1
// baseline (speedup 1.0000x reference)
#include <cuda_runtime.h>
#include <cstdint>

#define Bb 2
#define Sq 2048
#define Dm 1024
#define Hh 16
#define Dk 64

// Scratch (allocation-free rule: __device__ globals)
__device__ __align__(16) float g_qh[(size_t)Bb*Hh*Sq*Dk];
__device__ __align__(16) float g_kh[(size_t)Bb*Hh*Sq*Dk];
__device__ __align__(16) float g_vh[(size_t)Bb*Hh*Sq*Dk];
__device__ __align__(16) float g_ao[(size_t)Bb*Sq*Dm];

// ============================================================================
// K1: fused Q/K/V projection. Y = X @ W^T + b  (X: 4096x1024, W: 1024x1024)
// 128x128 block tile, BK=16, 8x8 per thread. Scatter epilogue to
// head layout: dst[((b*H+h)*S + s)*64 + d].
// blockIdx.z selects which of q/k/v.
// ============================================================================
__global__ __launch_bounds__(256) void proj_kernel(
    const float* __restrict__ xq, const float* __restrict__ xk, const float* __restrict__ xv,
    const float* __restrict__ wq, const float* __restrict__ wk, const float* __restrict__ wv,
    const float* __restrict__ bq, const float* __restrict__ bk, const float* __restrict__ bv)
{
    const int which = blockIdx.z;
    const float* __restrict__ A    = which == 0 ? xq : (which == 1 ? xk : xv);
    const float* __restrict__ W    = which == 0 ? wq : (which == 1 ? wk : wv);
    const float* __restrict__ bias = which == 0 ? bq : (which == 1 ? bk : bv);
    float* __restrict__ dst        = which == 0 ? g_qh : (which == 1 ? g_kh : g_vh);

    __shared__ float As[16][132];
    __shared__ float Bs[16][132];
    const int tid = threadIdx.x;
    const int tx = tid & 15, ty = tid >> 4;
    const int bm = blockIdx.y * 128;
    const int bn = blockIdx.x * 128;
    const int K = Dm;

    float acc[8][8];
#pragma unroll
    for (int i = 0; i < 8; i++)
#pragma unroll
        for (int j = 0; j < 8; j++) acc[i][j] = 0.f;

    for (int k0 = 0; k0 < K; k0 += 16) {
#pragma unroll
        for (int t = 0; t < 2; t++) {
            int f = tid + t * 256;
            int row = f >> 2;
            int kq = (f & 3) << 2;
            float4 va = *(const float4*)(A + (size_t)(bm + row) * K + k0 + kq);
            As[kq + 0][row] = va.x; As[kq + 1][row] = va.y;
            As[kq + 2][row] = va.z; As[kq + 3][row] = va.w;
            float4 vb = *(const float4*)(W + (size_t)(bn + row) * K + k0 + kq);
            Bs[kq + 0][row] = vb.x; Bs[kq + 1][row] = vb.y;
            Bs[kq + 2][row] = vb.z; Bs[kq + 3][row] = vb.w;
        }
        __syncthreads();
#pragma unroll
        for (int kk = 0; kk < 16; kk++) {
            float4 a0 = *(const float4*)&As[kk][ty * 8];
            float4 a1 = *(const float4*)&As[kk][ty * 8 + 4];
            float4 b0 = *(const float4*)&Bs[kk][tx * 8];
            float4 b1 = *(const float4*)&Bs[kk][tx * 8 + 4];
            float a[8] = {a0.x,a0.y,a0.z,a0.w,a1.x,a1.y,a1.z,a1.w};
            float b[8] = {b0.x,b0.y,b0.z,b0.w,b1.x,b1.y,b1.z,b1.w};
#pragma unroll
            for (int i = 0; i < 8; i++)
#pragma unroll
                for (int j = 0; j < 8; j++) acc[i][j] += a[i] * b[j];
        }
        __syncthreads();
    }

#pragma unroll
    for (int i = 0; i < 8; i++) {
        int m = bm + ty * 8 + i;
        int b = m >> 11;          // / Sq
        int s = m & (Sq - 1);
#pragma unroll
        for (int j = 0; j < 8; j += 4) {
            int n = bn + tx * 8 + j;
            int h = n >> 6;
            int d = n & 63;
            float4 v;
            v.x = acc[i][j + 0] + bias[n + 0];
            v.y = acc[i][j + 1] + bias[n + 1];
            v.z = acc[i][j + 2] + bias[n + 2];
            v.w = acc[i][j + 3] + bias[n + 3];
            *(float4*)(dst + (((size_t)(b * Hh + h) * Sq + s) << 6) + d) = v;
        }
    }
}

// ============================================================================
// K2: scores = (qh @ kh^T) * 0.125, masked. One block = 128(q) x 128(k), K=64.
// Writes raw (pre-softmax) scores directly into d_out scores region at
// sc[((b*S+q)*H + h)*S + k].
// ============================================================================
__global__ __launch_bounds__(256) void scores_kernel(
    const int* __restrict__ mask, float* __restrict__ sc)
{
    extern __shared__ float sdyn[];
    float (*Qt)[132] = (float(*)[132])sdyn;              // [d][q]
    float (*Kt)[132] = (float(*)[132])(sdyn + 64 * 132); // [d][k]

    const int bh = blockIdx.z;
    const int b = bh >> 4, h = bh & 15;
    const int q0 = blockIdx.y * 128, k0 = blockIdx.x * 128;
    const float* qp = g_qh + ((size_t)bh * Sq + q0) * Dk;
    const float* kp = g_kh + ((size_t)bh * Sq + k0) * Dk;
    const int tid = threadIdx.x, tx = tid & 15, ty = tid >> 4;

#pragma unroll
    for (int t = 0; t < 8; t++) {
        int f = tid + t * 256;     // 2048 float4 slots (128 rows x 16)
        int row = f >> 4;
        int c4 = (f & 15) << 2;
        float4 v = *(const float4*)(qp + row * Dk + c4);
        Qt[c4 + 0][row] = v.x; Qt[c4 + 1][row] = v.y;
        Qt[c4 + 2][row] = v.z; Qt[c4 + 3][row] = v.w;
        float4 w = *(const float4*)(kp + row * Dk + c4);
        Kt[c4 + 0][row] = w.x; Kt[c4 + 1][row] = w.y;
        Kt[c4 + 2][row] = w.z; Kt[c4 + 3][row] = w.w;
    }
    __syncthreads();

    float acc[8][8];
#pragma unroll
    for (int i = 0; i < 8; i++)
#pragma unroll
        for (int j = 0; j < 8; j++) acc[i][j] = 0.f;

#pragma unroll
    for (int d = 0; d < 64; d++) {
        float4 a0 = *(const float4*)&Qt[d][ty * 8];
        float4 a1 = *(const float4*)&Qt[d][ty * 8 + 4];
        float4 b0 = *(const float4*)&Kt[d][tx * 8];
        float4 b1 = *(const float4*)&Kt[d][tx * 8 + 4];
        float a[8] = {a0.x,a0.y,a0.z,a0.w,a1.x,a1.y,a1.z,a1.w};
        float bb[8] = {b0.x,b0.y,b0.z,b0.w,b1.x,b1.y,b1.z,b1.w};
#pragma unroll
        for (int i = 0; i < 8; i++)
#pragma unroll
            for (int j = 0; j < 8; j++) acc[i][j] += a[i] * bb[j];
    }

#pragma unroll
    for (int i = 0; i < 8; i++) {
        int qq = q0 + ty * 8 + i;
        const int4* mrow = (const int4*)(mask + ((size_t)b * Sq + qq) * Sq + k0 + tx * 8);
        float* orow = sc + (((size_t)(b * Sq + qq)) * Hh + h) * Sq + k0 + tx * 8;
        int4 m0 = mrow[0];
        int4 m1 = mrow[1];
        float4 v0, v1;
        v0.x = (m0.x == 0) ? -1000000000.0f : acc[i][0] * 0.125f;
        v0.y = (m0.y == 0) ? -1000000000.0f : acc[i][1] * 0.125f;
        v0.z = (m0.z == 0) ? -1000000000.0f : acc[i][2] * 0.125f;
        v0.w = (m0.w == 0) ? -1000000000.0f : acc[i][3] * 0.125f;
        v1.x = (m1.x == 0) ? -1000000000.0f : acc[i][4] * 0.125f;
        v1.y = (m1.y == 0) ? -1000000000.0f : acc[i][5] * 0.125f;
        v1.z = (m1.z == 0) ? -1000000000.0f : acc[i][6] * 0.125f;
        v1.w = (m1.w == 0) ? -1000000000.0f : acc[i][7] * 0.125f;
        *(float4*)(orow) = v0;
        *(float4*)(orow + 4) = v1;
    }
}

// ============================================================================
// K3: in-place row softmax over the last dim (row length S=2048).
// The scores region is exactly B*S*H contiguous rows of length S.
// ============================================================================
__global__ __launch_bounds__(256) void softmax_kernel(float* __restrict__ sc)
{
    float* p = sc + (size_t)blockIdx.x * Sq;
    const int tid = threadIdx.x;
    float4 a = *(const float4*)(p + tid * 4);
    float4 b = *(const float4*)(p + 1024 + tid * 4);

    float m = fmaxf(fmaxf(fmaxf(a.x, a.y), fmaxf(a.z, a.w)),
                    fmaxf(fmaxf(b.x, b.y), fmaxf(b.z, b.w)));
#pragma unroll
    for (int o = 16; o > 0; o >>= 1) m = fmaxf(m, __shfl_xor_sync(0xffffffffu, m, o));
    __shared__ float red[8];
    if ((tid & 31) == 0) red[tid >> 5] = m;
    __syncthreads();
    float M = red[0];
#pragma unroll
    for (int i = 1; i < 8; i++) M = fmaxf(M, red[i]);

    a.x = __expf(a.x - M); a.y = __expf(a.y - M);
    a.z = __expf(a.z - M); a.w = __expf(a.w - M);
    b.x = __expf(b.x - M); b.y = __expf(b.y - M);
    b.z = __expf(b.z - M); b.w = __expf(b.w - M);

    float s = (a.x + a.y + a.z + a.w) + (b.x + b.y + b.z + b.w);
#pragma unroll
    for (int o = 16; o > 0; o >>= 1) s += __shfl_xor_sync(0xffffffffu, s, o);
    __syncthreads();
    if ((tid & 31) == 0) red[tid >> 5] = s;
    __syncthreads();
    float S2 = red[0];
#pragma unroll
    for (int i = 1; i < 8; i++) S2 += red[i];

    float inv = 1.0f / S2;
    a.x *= inv; a.y *= inv; a.z *= inv; a.w *= inv;
    b.x *= inv; b.y *= inv; b.z *= inv; b.w *= inv;
    *(float4*)(p + tid * 4) = a;
    *(float4*)(p + 1024 + tid * 4) = b;
}

// ============================================================================
// K4: out_bh = attn_bh (2048x2048) @ vh_bh (2048x64).
// Block = 128(q) x 64(dk) tile, loop K over S in 64-chunks. 8x4 per thread.
// Writes to g_ao in (b,s,D) layout for the final projection.
// ============================================================================
__global__ __launch_bounds__(256) void av_kernel(const float* __restrict__ sc)
{
    extern __shared__ float sdyn[];
    float (*Pt)[132] = (float(*)[132])sdyn;             // [k][q]
    float (*Vt)[68]  = (float(*)[68])(sdyn + 64 * 132); // [k][d]

    const int bh = blockIdx.y;
    const int b = bh >> 4, h = bh & 15;
    const int q0 = blockIdx.x * 128;
    const float* vp = g_vh + (size_t)bh * Sq * Dk;
    const float* scb = sc + (size_t)b * Sq * Hh * Sq + (size_t)h * Sq;
    const int tid = threadIdx.x, tx = tid & 15, ty = tid >> 4;

    float acc[8][4];
#pragma unroll
    for (int i = 0; i < 8; i++)
#pragma unroll
        for (int j = 0; j < 4; j++) acc[i][j] = 0.f;

    for (int kt = 0; kt < Sq; kt += 64) {
#pragma unroll
        for (int t = 0; t < 8; t++) {   // attn tile: 128 q x 64 k
            int f = tid + t * 256;
            int row = f >> 4;           // q
            int c4 = (f & 15) << 2;     // k
            float4 v = *(const float4*)(scb + (size_t)(q0 + row) * (Hh * Sq) + kt + c4);
            Pt[c4 + 0][row] = v.x; Pt[c4 + 1][row] = v.y;
            Pt[c4 + 2][row] = v.z; Pt[c4 + 3][row] = v.w;
        }
#pragma unroll
        for (int t = 0; t < 4; t++) {   // vh tile: 64 k x 64 d
            int f = tid + t * 256;
            int row = f >> 4;
            int c4 = (f & 15) << 2;
            *(float4*)&Vt[row][c4] = *(const float4*)(vp + (size_t)(kt + row) * Dk + c4);
        }
        __syncthreads();
#pragma unroll
        for (int kk = 0; kk < 64; kk++) {
            float4 a0 = *(const float4*)&Pt[kk][ty * 8];
            float4 a1 = *(const float4*)&Pt[kk][ty * 8 + 4];
            float4 bv = *(const float4*)&Vt[kk][tx * 4];
            float a[8] = {a0.x,a0.y,a0.z,a0.w,a1.x,a1.y,a1.z,a1.w};
            float bb[4] = {bv.x,bv.y,bv.z,bv.w};
#pragma unroll
            for (int i = 0; i < 8; i++)
#pragma unroll
                for (int j = 0; j < 4; j++) acc[i][j] += a[i] * bb[j];
        }
        __syncthreads();
    }

#pragma unroll
    for (int i = 0; i < 8; i++) {
        float4 v = make_float4(acc[i][0], acc[i][1], acc[i][2], acc[i][3]);
        *(float4*)(g_ao + (size_t)(b * Sq + q0 + ty * 8 + i) * Dm + h * Dk + tx * 4) = v;
    }
}

// ============================================================================
// K5: final projection out = g_ao @ Wo^T + bo  (4096x1024 @ 1024x1024)
// ============================================================================
__global__ __launch_bounds__(256) void outproj_kernel(
    const float* __restrict__ W, const float* __restrict__ bias, float* __restrict__ C)
{
    __shared__ float As[16][132];
    __shared__ float Bs[16][132];
    const int tid = threadIdx.x;
    const int tx = tid & 15, ty = tid >> 4;
    const int bm = blockIdx.y * 128;
    const int bn = blockIdx.x * 128;
    const int K = Dm;
    const float* __restrict__ A = g_ao;

    float acc[8][8];
#pragma unroll
    for (int i = 0; i < 8; i++)
#pragma unroll
        for (int j = 0; j < 8; j++) acc[i][j] = 0.f;

    for (int k0 = 0; k0 < K; k0 += 16) {
#pragma unroll
        for (int t = 0; t < 2; t++) {
            int f = tid + t * 256;
            int row = f >> 2;
            int kq = (f & 3) << 2;
            float4 va = *(const float4*)(A + (size_t)(bm + row) * K + k0 + kq);
            As[kq + 0][row] = va.x; As[kq + 1][row] = va.y;
            As[kq + 2][row] = va.z; As[kq + 3][row] = va.w;
            float4 vb = *(const float4*)(W + (size_t)(bn + row) * K + k0 + kq);
            Bs[kq + 0][row] = vb.x; Bs[kq + 1][row] = vb.y;
            Bs[kq + 2][row] = vb.z; Bs[kq + 3][row] = vb.w;
        }
        __syncthreads();
#pragma unroll
        for (int kk = 0; kk < 16; kk++) {
            float4 a0 = *(const float4*)&As[kk][ty * 8];
            float4 a1 = *(const float4*)&As[kk][ty * 8 + 4];
            float4 b0 = *(const float4*)&Bs[kk][tx * 8];
            float4 b1 = *(const float4*)&Bs[kk][tx * 8 + 4];
            float a[8] = {a0.x,a0.y,a0.z,a0.w,a1.x,a1.y,a1.z,a1.w};
            float b[8] = {b0.x,b0.y,b0.z,b0.w,b1.x,b1.y,b1.z,b1.w};
#pragma unroll
            for (int i = 0; i < 8; i++)
#pragma unroll
                for (int j = 0; j < 8; j++) acc[i][j] += a[i] * b[j];
        }
        __syncthreads();
    }

#pragma unroll
    for (int i = 0; i < 8; i++) {
        int m = bm + ty * 8 + i;
#pragma unroll
        for (int j = 0; j < 8; j += 4) {
            int n = bn + tx * 8 + j;
            float4 v;
            v.x = acc[i][j + 0] + bias[n + 0];
            v.y = acc[i][j + 1] + bias[n + 1];
            v.z = acc[i][j + 2] + bias[n + 2];
            v.w = acc[i][j + 3] + bias[n + 3];
            *(float4*)(C + (size_t)m * Dm + n) = v;
        }
    }
}

// ============================================================================
extern "C" void kernel_launch(void* const* d_in, const int* in_sizes, int n_in,
                              void* d_out, int out_size)
{
    const float* q    = (const float*)d_in[0];
    const float* k    = (const float*)d_in[1];
    const float* v    = (const float*)d_in[2];
    const int*   mask = (const int*)d_in[3];
    const float* Wq   = (const float*)d_in[4];
    const float* bq   = (const float*)d_in[5];
    const float* Wk   = (const float*)d_in[6];
    const float* bk   = (const float*)d_in[7];
    const float* Wv   = (const float*)d_in[8];
    const float* bv   = (const float*)d_in[9];
    const float* Wo   = (const float*)d_in[10];
    const float* bo   = (const float*)d_in[11];

    float* out = (float*)d_out;
    float* sc  = out + (size_t)Bb * Sq * Dm;   // scores_out region

    const int scores_smem = 64 * 132 * 2 * 4;            // 67584 B
    const int av_smem     = (64 * 132 + 64 * 68) * 4;    // 51200 B
    cudaFuncSetAttribute(scores_kernel, cudaFuncAttributeMaxDynamicSharedMemorySize, scores_smem);
    cudaFuncSetAttribute(av_kernel,     cudaFuncAttributeMaxDynamicSharedMemorySize, av_smem);

    dim3 gp(Dm / 128, (Bb * Sq) / 128, 3);
    proj_kernel<<<gp, 256>>>(q, k, v, Wq, Wk, Wv, bq, bk, bv);

    dim3 gs(Sq / 128, Sq / 128, Bb * Hh);
    scores_kernel<<<gs, 256, scores_smem>>>(mask, sc);

    softmax_kernel<<<Bb * Hh * Sq, 256>>>(sc);

    dim3 ga(Sq / 128, Bb * Hh);
    av_kernel<<<ga, 256, av_smem>>>(sc);

    dim3 go(Dm / 128, (Bb * Sq) / 128);
    outproj_kernel<<<go, 256>>>(Wo, bo, out);
}

// round 2
// speedup vs baseline: 1.4716x; 1.4716x over previous
#include <cuda_runtime.h>
#include <cstdint>

#define Bb 2
#define Sq 2048
#define Dm 1024
#define Hh 16
#define Dk 64

// Scratch (allocation-free rule: __device__ globals)
__device__ __align__(16) float g_qh[(size_t)Bb*Hh*Sq*Dk];
__device__ __align__(16) float g_kh[(size_t)Bb*Hh*Sq*Dk];
__device__ __align__(16) float g_vh[(size_t)Bb*Hh*Sq*Dk];
__device__ __align__(16) float g_ao[(size_t)Bb*Sq*Dm];

// ---------------------------------------------------------------------------
// tf32 helpers
// ---------------------------------------------------------------------------
__device__ __forceinline__ uint32_t f2tf(float x) {
    uint32_t u;
    asm("cvt.rna.tf32.f32 %0, %1;" : "=r"(u) : "f"(x));
    return u;
}

__device__ __forceinline__ void mma_tf32(float c[4],
    uint32_t a0, uint32_t a1, uint32_t a2, uint32_t a3,
    uint32_t b0, uint32_t b1)
{
    asm volatile(
        "mma.sync.aligned.m16n8k8.row.col.f32.tf32.tf32.f32 "
        "{%0,%1,%2,%3}, {%4,%5,%6,%7}, {%8,%9}, {%0,%1,%2,%3};"
        : "+f"(c[0]), "+f"(c[1]), "+f"(c[2]), "+f"(c[3])
        : "r"(a0), "r"(a1), "r"(a2), "r"(a3), "r"(b0), "r"(b1));
}

// ============================================================================
// K1: fused Q/K/V projection (tf32 MMA). Y = X @ W^T + b.
// 128x128 block, BK=16, 8 warps as 2(m) x 4(n), warp tile 64x32.
// Scatter epilogue to head layout dst[((b*H+h)*S+s)*64+d].
// ============================================================================
__global__ __launch_bounds__(256) void proj_tc(
    const float* __restrict__ xq, const float* __restrict__ xk, const float* __restrict__ xv,
    const float* __restrict__ wq, const float* __restrict__ wk, const float* __restrict__ wv,
    const float* __restrict__ bq, const float* __restrict__ bk, const float* __restrict__ bv)
{
    const int which = blockIdx.z;
    const float* __restrict__ A    = which == 0 ? xq : (which == 1 ? xk : xv);
    const float* __restrict__ W    = which == 0 ? wq : (which == 1 ? wk : wv);
    const float* __restrict__ bias = which == 0 ? bq : (which == 1 ? bk : bv);
    float* __restrict__ dst        = which == 0 ? g_qh : (which == 1 ? g_kh : g_vh);

    __shared__ uint32_t As[16][136];   // [k][m]
    __shared__ uint32_t Bs[16][136];   // [k][n]

    const int tid = threadIdx.x;
    const int lane = tid & 31, wid = tid >> 5;
    const int wm = wid & 1, wn = wid >> 1;
    const int bm = blockIdx.y * 128, bn = blockIdx.x * 128;
    const int lr = lane >> 2, lc = lane & 3;

    float acc[4][4][4];
#pragma unroll
    for (int i = 0; i < 4; i++)
#pragma unroll
        for (int j = 0; j < 4; j++)
#pragma unroll
            for (int t = 0; t < 4; t++) acc[i][j][t] = 0.f;

    for (int k0 = 0; k0 < Dm; k0 += 16) {
#pragma unroll
        for (int t = 0; t < 2; t++) {
            int f = tid + t * 256;
            int row = f >> 2;
            int kq = (f & 3) << 2;
            float4 va = *(const float4*)(A + (size_t)(bm + row) * Dm + k0 + kq);
            As[kq + 0][row] = f2tf(va.x); As[kq + 1][row] = f2tf(va.y);
            As[kq + 2][row] = f2tf(va.z); As[kq + 3][row] = f2tf(va.w);
            float4 vb = *(const float4*)(W + (size_t)(bn + row) * Dm + k0 + kq);
            Bs[kq + 0][row] = f2tf(vb.x); Bs[kq + 1][row] = f2tf(vb.y);
            Bs[kq + 2][row] = f2tf(vb.z); Bs[kq + 3][row] = f2tf(vb.w);
        }
        __syncthreads();
#pragma unroll
        for (int ks = 0; ks < 16; ks += 8) {
            uint32_t af[4][4], bf[4][2];
#pragma unroll
            for (int mt = 0; mt < 4; mt++) {
                int rb = wm * 64 + mt * 16 + lr;
                af[mt][0] = As[ks + lc][rb];
                af[mt][1] = As[ks + lc][rb + 8];
                af[mt][2] = As[ks + 4 + lc][rb];
                af[mt][3] = As[ks + 4 + lc][rb + 8];
            }
#pragma unroll
            for (int nt = 0; nt < 4; nt++) {
                int nb = wn * 32 + nt * 8 + lr;
                bf[nt][0] = Bs[ks + lc][nb];
                bf[nt][1] = Bs[ks + 4 + lc][nb];
            }
#pragma unroll
            for (int mt = 0; mt < 4; mt++)
#pragma unroll
                for (int nt = 0; nt < 4; nt++)
                    mma_tf32(acc[mt][nt], af[mt][0], af[mt][1], af[mt][2], af[mt][3],
                             bf[nt][0], bf[nt][1]);
        }
        __syncthreads();
    }

#pragma unroll
    for (int mt = 0; mt < 4; mt++) {
#pragma unroll
        for (int nt = 0; nt < 4; nt++) {
            int col = bn + wn * 32 + nt * 8 + lc * 2;
            int h = col >> 6, d = col & 63;
            float b0 = bias[col], b1 = bias[col + 1];
#pragma unroll
            for (int half = 0; half < 2; half++) {
                int m = bm + wm * 64 + mt * 16 + lr + half * 8;
                int b = m >> 11;
                int s = m & (Sq - 1);
                float2 v;
                v.x = acc[mt][nt][half * 2 + 0] + b0;
                v.y = acc[mt][nt][half * 2 + 1] + b1;
                *(float2*)(dst + (((size_t)(b * Hh + h) * Sq + s) << 6) + d) = v;
            }
        }
    }
}

// ============================================================================
// K2: scores = (qh @ kh^T) * 0.125, masked (tf32 MMA).
// Block = 128(q) x 128(k), full K=64 in smem. Writes raw scores into d_out.
// ============================================================================
__global__ __launch_bounds__(256) void scores_tc(
    const int* __restrict__ mask, float* __restrict__ sc)
{
    extern __shared__ uint32_t sdyn[];
    uint32_t (*Qs)[136] = (uint32_t(*)[136])sdyn;             // [d][q]
    uint32_t (*Ks)[136] = (uint32_t(*)[136])(sdyn + 64 * 136); // [d][k]

    const int bh = blockIdx.z;
    const int b = bh >> 4, h = bh & 15;
    const int q0 = blockIdx.y * 128, k0 = blockIdx.x * 128;
    const float* qp = g_qh + ((size_t)bh * Sq + q0) * Dk;
    const float* kp = g_kh + ((size_t)bh * Sq + k0) * Dk;
    const int tid = threadIdx.x;
    const int lane = tid & 31, wid = tid >> 5;
    const int wm = wid & 1, wn = wid >> 1;
    const int lr = lane >> 2, lc = lane & 3;

#pragma unroll
    for (int t = 0; t < 8; t++) {
        int f = tid + t * 256;
        int row = f >> 4;
        int c4 = (f & 15) << 2;
        float4 v = *(const float4*)(qp + row * Dk + c4);
        Qs[c4 + 0][row] = f2tf(v.x); Qs[c4 + 1][row] = f2tf(v.y);
        Qs[c4 + 2][row] = f2tf(v.z); Qs[c4 + 3][row] = f2tf(v.w);
        float4 w = *(const float4*)(kp + row * Dk + c4);
        Ks[c4 + 0][row] = f2tf(w.x); Ks[c4 + 1][row] = f2tf(w.y);
        Ks[c4 + 2][row] = f2tf(w.z); Ks[c4 + 3][row] = f2tf(w.w);
    }
    __syncthreads();

    float acc[4][4][4];
#pragma unroll
    for (int i = 0; i < 4; i++)
#pragma unroll
        for (int j = 0; j < 4; j++)
#pragma unroll
            for (int t = 0; t < 4; t++) acc[i][j][t] = 0.f;

#pragma unroll
    for (int ks = 0; ks < 64; ks += 8) {
        uint32_t af[4][4], bf[4][2];
#pragma unroll
        for (int mt = 0; mt < 4; mt++) {
            int rb = wm * 64 + mt * 16 + lr;
            af[mt][0] = Qs[ks + lc][rb];
            af[mt][1] = Qs[ks + lc][rb + 8];
            af[mt][2] = Qs[ks + 4 + lc][rb];
            af[mt][3] = Qs[ks + 4 + lc][rb + 8];
        }
#pragma unroll
        for (int nt = 0; nt < 4; nt++) {
            int nb = wn * 32 + nt * 8 + lr;
            bf[nt][0] = Ks[ks + lc][nb];
            bf[nt][1] = Ks[ks + 4 + lc][nb];
        }
#pragma unroll
        for (int mt = 0; mt < 4; mt++)
#pragma unroll
            for (int nt = 0; nt < 4; nt++)
                mma_tf32(acc[mt][nt], af[mt][0], af[mt][1], af[mt][2], af[mt][3],
                         bf[nt][0], bf[nt][1]);
    }

#pragma unroll
    for (int mt = 0; mt < 4; mt++) {
#pragma unroll
        for (int half = 0; half < 2; half++) {
            int qq = q0 + wm * 64 + mt * 16 + lr + half * 8;
            const int* mrow = mask + ((size_t)b * Sq + qq) * Sq + k0;
            float* orow = sc + (((size_t)(b * Sq + qq)) * Hh + h) * Sq + k0;
#pragma unroll
            for (int nt = 0; nt < 4; nt++) {
                int kc = wn * 32 + nt * 8 + lc * 2;
                int2 m2 = *(const int2*)(mrow + kc);
                float2 v;
                v.x = (m2.x == 0) ? -1000000000.0f : acc[mt][nt][half * 2 + 0] * 0.125f;
                v.y = (m2.y == 0) ? -1000000000.0f : acc[mt][nt][half * 2 + 1] * 0.125f;
                *(float2*)(orow + kc) = v;
            }
        }
    }
}

// ============================================================================
// K3: in-place row softmax over last dim (row length S=2048).
// ============================================================================
__global__ __launch_bounds__(256) void softmax_kernel(float* __restrict__ sc)
{
    float* p = sc + (size_t)blockIdx.x * Sq;
    const int tid = threadIdx.x;
    float4 a = *(const float4*)(p + tid * 4);
    float4 b = *(const float4*)(p + 1024 + tid * 4);

    float m = fmaxf(fmaxf(fmaxf(a.x, a.y), fmaxf(a.z, a.w)),
                    fmaxf(fmaxf(b.x, b.y), fmaxf(b.z, b.w)));
#pragma unroll
    for (int o = 16; o > 0; o >>= 1) m = fmaxf(m, __shfl_xor_sync(0xffffffffu, m, o));
    __shared__ float red[8];
    if ((tid & 31) == 0) red[tid >> 5] = m;
    __syncthreads();
    float M = red[0];
#pragma unroll
    for (int i = 1; i < 8; i++) M = fmaxf(M, red[i]);

    a.x = __expf(a.x - M); a.y = __expf(a.y - M);
    a.z = __expf(a.z - M); a.w = __expf(a.w - M);
    b.x = __expf(b.x - M); b.y = __expf(b.y - M);
    b.z = __expf(b.z - M); b.w = __expf(b.w - M);

    float s = (a.x + a.y + a.z + a.w) + (b.x + b.y + b.z + b.w);
#pragma unroll
    for (int o = 16; o > 0; o >>= 1) s += __shfl_xor_sync(0xffffffffu, s, o);
    __syncthreads();
    if ((tid & 31) == 0) red[tid >> 5] = s;
    __syncthreads();
    float S2 = red[0];
#pragma unroll
    for (int i = 1; i < 8; i++) S2 += red[i];

    float inv = 1.0f / S2;
    a.x *= inv; a.y *= inv; a.z *= inv; a.w *= inv;
    b.x *= inv; b.y *= inv; b.z *= inv; b.w *= inv;
    *(float4*)(p + tid * 4) = a;
    *(float4*)(p + 1024 + tid * 4) = b;
}

// ============================================================================
// K4: out_bh = attn_bh (2048x2048) @ vh_bh (2048x64)  (tf32 MMA).
// Block = 128(q) x 64(d), BK=32, 8 warps as 4(m) x 2(n), warp tile 32x32.
// ============================================================================
__global__ __launch_bounds__(256) void av_tc(const float* __restrict__ sc)
{
    __shared__ uint32_t Ps[32][136];  // [k][q]
    __shared__ uint32_t Vs[32][72];   // [k][d]

    const int bh = blockIdx.y;
    const int b = bh >> 4, h = bh & 15;
    const int q0 = blockIdx.x * 128;
    const float* vp = g_vh + (size_t)bh * Sq * Dk;
    const float* scb = sc + (size_t)b * Sq * Hh * Sq + (size_t)h * Sq;
    const int tid = threadIdx.x;
    const int lane = tid & 31, wid = tid >> 5;
    const int wm = wid >> 1, wn = wid & 1;
    const int lr = lane >> 2, lc = lane & 3;
    const size_t HS = (size_t)Hh * Sq;

    float acc[2][4][4];
#pragma unroll
    for (int i = 0; i < 2; i++)
#pragma unroll
        for (int j = 0; j < 4; j++)
#pragma unroll
            for (int t = 0; t < 4; t++) acc[i][j][t] = 0.f;

    for (int kt = 0; kt < Sq; kt += 32) {
#pragma unroll
        for (int t = 0; t < 4; t++) {           // attn: 128 q x 32 k
            int f = tid + t * 256;
            int row = f >> 3;
            int c4 = (f & 7) << 2;
            float4 v = *(const float4*)(scb + (size_t)(q0 + row) * HS + kt + c4);
            Ps[c4 + 0][row] = f2tf(v.x); Ps[c4 + 1][row] = f2tf(v.y);
            Ps[c4 + 2][row] = f2tf(v.z); Ps[c4 + 3][row] = f2tf(v.w);
        }
#pragma unroll
        for (int t = 0; t < 2; t++) {           // vh: 32 k x 64 d
            int f = tid + t * 256;
            int row = f >> 4;
            int c4 = (f & 15) << 2;
            float4 v = *(const float4*)(vp + (size_t)(kt + row) * Dk + c4);
            Vs[row][c4 + 0] = f2tf(v.x); Vs[row][c4 + 1] = f2tf(v.y);
            Vs[row][c4 + 2] = f2tf(v.z); Vs[row][c4 + 3] = f2tf(v.w);
        }
        __syncthreads();
#pragma unroll
        for (int ks = 0; ks < 32; ks += 8) {
            uint32_t af[2][4], bf[4][2];
#pragma unroll
            for (int mt = 0; mt < 2; mt++) {
                int rb = wm * 32 + mt * 16 + lr;
                af[mt][0] = Ps[ks + lc][rb];
                af[mt][1] = Ps[ks + lc][rb + 8];
                af[mt][2] = Ps[ks + 4 + lc][rb];
                af[mt][3] = Ps[ks + 4 + lc][rb + 8];
            }
#pragma unroll
            for (int nt = 0; nt < 4; nt++) {
                int nb = wn * 32 + nt * 8 + lr;
                bf[nt][0] = Vs[ks + lc][nb];
                bf[nt][1] = Vs[ks + 4 + lc][nb];
            }
#pragma unroll
            for (int mt = 0; mt < 2; mt++)
#pragma unroll
                for (int nt = 0; nt < 4; nt++)
                    mma_tf32(acc[mt][nt], af[mt][0], af[mt][1], af[mt][2], af[mt][3],
                             bf[nt][0], bf[nt][1]);
        }
        __syncthreads();
    }

#pragma unroll
    for (int mt = 0; mt < 2; mt++) {
#pragma unroll
        for (int half = 0; half < 2; half++) {
            int q = q0 + wm * 32 + mt * 16 + lr + half * 8;
            float* orow = g_ao + (size_t)(b * Sq + q) * Dm + h * Dk;
#pragma unroll
            for (int nt = 0; nt < 4; nt++) {
                int d = wn * 32 + nt * 8 + lc * 2;
                float2 v;
                v.x = acc[mt][nt][half * 2 + 0];
                v.y = acc[mt][nt][half * 2 + 1];
                *(float2*)(orow + d) = v;
            }
        }
    }
}

// ============================================================================
// K5: final projection out = g_ao @ Wo^T + bo  (tf32 MMA)
// ============================================================================
__global__ __launch_bounds__(256) void outproj_tc(
    const float* __restrict__ W, const float* __restrict__ bias, float* __restrict__ C)
{
    __shared__ uint32_t As[16][136];
    __shared__ uint32_t Bs[16][136];
    const int tid = threadIdx.x;
    const int lane = tid & 31, wid = tid >> 5;
    const int wm = wid & 1, wn = wid >> 1;
    const int bm = blockIdx.y * 128, bn = blockIdx.x * 128;
    const int lr = lane >> 2, lc = lane & 3;
    const float* __restrict__ A = g_ao;

    float acc[4][4][4];
#pragma unroll
    for (int i = 0; i < 4; i++)
#pragma unroll
        for (int j = 0; j < 4; j++)
#pragma unroll
            for (int t = 0; t < 4; t++) acc[i][j][t] = 0.f;

    for (int k0 = 0; k0 < Dm; k0 += 16) {
#pragma unroll
        for (int t = 0; t < 2; t++) {
            int f = tid + t * 256;
            int row = f >> 2;
            int kq = (f & 3) << 2;
            float4 va = *(const float4*)(A + (size_t)(bm + row) * Dm + k0 + kq);
            As[kq + 0][row] = f2tf(va.x); As[kq + 1][row] = f2tf(va.y);
            As[kq + 2][row] = f2tf(va.z); As[kq + 3][row] = f2tf(va.w);
            float4 vb = *(const float4*)(W + (size_t)(bn + row) * Dm + k0 + kq);
            Bs[kq + 0][row] = f2tf(vb.x); Bs[kq + 1][row] = f2tf(vb.y);
            Bs[kq + 2][row] = f2tf(vb.z); Bs[kq + 3][row] = f2tf(vb.w);
        }
        __syncthreads();
#pragma unroll
        for (int ks = 0; ks < 16; ks += 8) {
            uint32_t af[4][4], bf[4][2];
#pragma unroll
            for (int mt = 0; mt < 4; mt++) {
                int rb = wm * 64 + mt * 16 + lr;
                af[mt][0] = As[ks + lc][rb];
                af[mt][1] = As[ks + lc][rb + 8];
                af[mt][2] = As[ks + 4 + lc][rb];
                af[mt][3] = As[ks + 4 + lc][rb + 8];
            }
#pragma unroll
            for (int nt = 0; nt < 4; nt++) {
                int nb = wn * 32 + nt * 8 + lr;
                bf[nt][0] = Bs[ks + lc][nb];
                bf[nt][1] = Bs[ks + 4 + lc][nb];
            }
#pragma unroll
            for (int mt = 0; mt < 4; mt++)
#pragma unroll
                for (int nt = 0; nt < 4; nt++)
                    mma_tf32(acc[mt][nt], af[mt][0], af[mt][1], af[mt][2], af[mt][3],
                             bf[nt][0], bf[nt][1]);
        }
        __syncthreads();
    }

#pragma unroll
    for (int mt = 0; mt < 4; mt++) {
#pragma unroll
        for (int nt = 0; nt < 4; nt++) {
            int col = bn + wn * 32 + nt * 8 + lc * 2;
            float b0 = bias[col], b1 = bias[col + 1];
#pragma unroll
            for (int half = 0; half < 2; half++) {
                int m = bm + wm * 64 + mt * 16 + lr + half * 8;
                float2 v;
                v.x = acc[mt][nt][half * 2 + 0] + b0;
                v.y = acc[mt][nt][half * 2 + 1] + b1;
                *(float2*)(C + (size_t)m * Dm + col) = v;
            }
        }
    }
}

// ============================================================================
extern "C" void kernel_launch(void* const* d_in, const int* in_sizes, int n_in,
                              void* d_out, int out_size)
{
    const float* q    = (const float*)d_in[0];
    const float* k    = (const float*)d_in[1];
    const float* v    = (const float*)d_in[2];
    const int*   mask = (const int*)d_in[3];
    const float* Wq   = (const float*)d_in[4];
    const float* bq   = (const float*)d_in[5];
    const float* Wk   = (const float*)d_in[6];
    const float* bk   = (const float*)d_in[7];
    const float* Wv   = (const float*)d_in[8];
    const float* bv   = (const float*)d_in[9];
    const float* Wo   = (const float*)d_in[10];
    const float* bo   = (const float*)d_in[11];

    float* out = (float*)d_out;
    float* sc  = out + (size_t)Bb * Sq * Dm;   // scores_out region

    const int scores_smem = 2 * 64 * 136 * 4;  // 69632 B
    cudaFuncSetAttribute(scores_tc, cudaFuncAttributeMaxDynamicSharedMemorySize, scores_smem);

    dim3 gp(Dm / 128, (Bb * Sq) / 128, 3);
    proj_tc<<<gp, 256>>>(q, k, v, Wq, Wk, Wv, bq, bk, bv);

    dim3 gs(Sq / 128, Sq / 128, Bb * Hh);
    scores_tc<<<gs, 256, scores_smem>>>(mask, sc);

    softmax_kernel<<<Bb * Hh * Sq, 256>>>(sc);

    dim3 ga(Sq / 128, Bb * Hh);
    av_tc<<<ga, 256>>>(sc);

    dim3 go(Dm / 128, (Bb * Sq) / 128);
    outproj_tc<<<go, 256>>>(Wo, bo, out);
}